// round 1
// baseline (speedup 1.0000x reference)
#include <cuda_runtime.h>
#include <cuda_bf16.h>
#include <math.h>

// ---------------------------------------------------------------------------
// SLAYER SRM-alpha 2-layer SNN.
//   x  : (8, 32768, 300) fp32, binary {0,1}, ~3% density
//   w1 : (410, 32768) fp32
//   w2 : (10, 410) fp32
//   out: (8, 10, 300) fp32 spikes
//
// Layer GEMMs exploit exact binary inputs: z[col][o] = sum over active i of w[o,i].
// PSP is the exact truncated 100-tap SRM-alpha FIR. Spike scan is the exact
// fp32 recurrence (contraction disabled) to match the reference bitwise-close.
// ---------------------------------------------------------------------------

#define N_BATCH 8
#define I_DIM   32768
#define O1      410
#define O1_PAD  416      // padded w1t row (float4-friendly)
#define O2      10
#define T_DIM   300
#define K_FIR   100
#define IDX_CAP 2048     // >> max nnz per column (mean 983, sigma ~31)
#define NCOLS   (N_BATCH * T_DIM)

// fp32 constants exactly matching float(np.exp(-1.0)) and float(-20*np.e)
#define A_REF_F 0.36787944117144233f
#define K_REF_F -54.365636569180902f
#define THETA_F 10.0f

// --- scratch (device globals: allocation-free) ---
__device__ float          g_w1t[(size_t)I_DIM * O1_PAD];   // 54.5 MB, (i, o) padded
__device__ unsigned short g_idx[(size_t)NCOLS * IDX_CAP];  // 9.8 MB
__device__ int            g_cnt[NCOLS];
__device__ float          g_z1[(size_t)N_BATCH * O1 * T_DIM];
__device__ float          g_u1[(size_t)N_BATCH * O1 * T_DIM];
__device__ float          g_s1[(size_t)N_BATCH * O1 * T_DIM];
__device__ float          g_z2[(size_t)N_BATCH * O2 * T_DIM];
__device__ float          g_u2[(size_t)N_BATCH * O2 * T_DIM];

// ---------------------------------------------------------------------------
// 1) w1 (O,I) -> w1t (I, O1_PAD), zero-padded cols 410..415
// ---------------------------------------------------------------------------
__global__ void w1t_kernel(const float* __restrict__ w1) {
    __shared__ float tile[32][33];
    int i0 = blockIdx.x * 32;
    int o0 = blockIdx.y * 32;
    int tx = threadIdx.x, ty = threadIdx.y;

    int o_in = o0 + ty;
    int i_in = i0 + tx;
    tile[ty][tx] = (o_in < O1) ? w1[(size_t)o_in * I_DIM + i_in] : 0.0f;
    __syncthreads();

    int i_out = i0 + ty;
    int o_out = o0 + tx;   // o0 max = 12*32 = 384, +31 = 415 < 416 always OK
    g_w1t[(size_t)i_out * O1_PAD + o_out] = tile[tx][ty];
}

// ---------------------------------------------------------------------------
// 2) Deterministic ordered compaction: per (n,t) list of active i (uint16).
//    grid (8, 10), block 256. CTA handles 32 t-columns, iterating i-chunks of
//    128 in order; warp ballot-scan preserves ascending-i order.
// ---------------------------------------------------------------------------
__global__ void compact_kernel(const float* __restrict__ x) {
    __shared__ float tile[128][33];   // [i_local][t_local], pad to kill conflicts
    int n  = blockIdx.x;
    int t0 = blockIdx.y * 32;
    int tid  = threadIdx.x;
    int wid  = tid >> 5;
    int lane = tid & 31;

    int base0 = 0, base1 = 0, base2 = 0, base3 = 0;

    int tld = t0 + lane;
    for (int c = 0; c < I_DIM / 128; ++c) {
        int i0 = c * 128;
        // coalesced load: each warp loads 16 rows of 32 consecutive t
        #pragma unroll
        for (int k = 0; k < 16; ++k) {
            int r = wid * 16 + k;
            tile[r][lane] = (tld < T_DIM)
                ? x[((size_t)n * I_DIM + i0 + r) * T_DIM + tld] : 0.0f;
        }
        __syncthreads();

        // each warp compacts 4 columns
        #pragma unroll
        for (int cc = 0; cc < 4; ++cc) {
            int tl = wid * 4 + cc;
            int tg = t0 + tl;
            if (tg < T_DIM) {
                int* basep = (cc == 0) ? &base0 : (cc == 1) ? &base1
                           : (cc == 2) ? &base2 : &base3;
                size_t obase = (size_t)(n * T_DIM + tg) * IDX_CAP;
                #pragma unroll
                for (int j = 0; j < 4; ++j) {
                    float v = tile[j * 32 + lane][tl];
                    unsigned b = __ballot_sync(0xffffffffu, v != 0.0f);
                    if (v != 0.0f) {
                        int rank = __popc(b & ((1u << lane) - 1u));
                        g_idx[obase + *basep + rank] =
                            (unsigned short)(i0 + j * 32 + lane);
                    }
                    *basep += __popc(b);
                }
            }
        }
        __syncthreads();
    }

    if (lane == 0) {
        int tg0 = t0 + wid * 4;
        if (tg0 + 0 < T_DIM) g_cnt[n * T_DIM + tg0 + 0] = base0;
        if (tg0 + 1 < T_DIM) g_cnt[n * T_DIM + tg0 + 1] = base1;
        if (tg0 + 2 < T_DIM) g_cnt[n * T_DIM + tg0 + 2] = base2;
        if (tg0 + 3 < T_DIM) g_cnt[n * T_DIM + tg0 + 3] = base3;
    }
}

// ---------------------------------------------------------------------------
// 3) Layer-1 gather-sum GEMM. CTA per (n,t) column. Threads 0..103 each hold
//    a float4 of outputs; loop over active-i list summing w1t rows (x == 1.0).
// ---------------------------------------------------------------------------
__global__ void __launch_bounds__(128) g1_kernel() {
    int col = blockIdx.x;            // n*300 + t
    int n = col / T_DIM, t = col % T_DIM;
    int cnt = g_cnt[col];

    __shared__ unsigned short sidx[IDX_CAP];
    for (int k = threadIdx.x; k < cnt; k += 128)
        sidx[k] = g_idx[(size_t)col * IDX_CAP + k];
    __syncthreads();

    int tid = threadIdx.x;
    float4 acc = make_float4(0.f, 0.f, 0.f, 0.f);
    if (tid < 104) {
        const float4* w4 = reinterpret_cast<const float4*>(g_w1t);
        int k = 0;
        for (; k + 4 <= cnt; k += 4) {
            float4 a0 = w4[(size_t)sidx[k + 0] * (O1_PAD / 4) + tid];
            float4 a1 = w4[(size_t)sidx[k + 1] * (O1_PAD / 4) + tid];
            float4 a2 = w4[(size_t)sidx[k + 2] * (O1_PAD / 4) + tid];
            float4 a3 = w4[(size_t)sidx[k + 3] * (O1_PAD / 4) + tid];
            acc.x += a0.x; acc.y += a0.y; acc.z += a0.z; acc.w += a0.w;
            acc.x += a1.x; acc.y += a1.y; acc.z += a1.z; acc.w += a1.w;
            acc.x += a2.x; acc.y += a2.y; acc.z += a2.z; acc.w += a2.w;
            acc.x += a3.x; acc.y += a3.y; acc.z += a3.z; acc.w += a3.w;
        }
        for (; k < cnt; ++k) {
            float4 a0 = w4[(size_t)sidx[k] * (O1_PAD / 4) + tid];
            acc.x += a0.x; acc.y += a0.y; acc.z += a0.z; acc.w += a0.w;
        }
        int o0 = tid * 4;
        size_t zb = ((size_t)n * O1) * T_DIM + t;
        if (o0 + 0 < O1) g_z1[zb + (size_t)(o0 + 0) * T_DIM] = acc.x;
        if (o0 + 1 < O1) g_z1[zb + (size_t)(o0 + 1) * T_DIM] = acc.y;
        if (o0 + 2 < O1) g_z1[zb + (size_t)(o0 + 2) * T_DIM] = acc.z;
        if (o0 + 3 < O1) g_z1[zb + (size_t)(o0 + 3) * T_DIM] = acc.w;
    }
}

// ---------------------------------------------------------------------------
// 4/7) PSP: exact truncated 100-tap SRM-alpha FIR along t. CTA per row.
//      eps[m] = (m/10) * exp(1 - m/10), eps[0] = 0.
// ---------------------------------------------------------------------------
__global__ void psp_kernel(const float* __restrict__ z, float* __restrict__ u) {
    __shared__ float sz[T_DIM];
    __shared__ float se[K_FIR];
    int row = blockIdx.x;
    int tid = threadIdx.x;   // 320

    if (tid < T_DIM) sz[tid] = z[(size_t)row * T_DIM + tid];
    if (tid < K_FIR) {
        float a = (float)tid / 10.0f;
        se[tid] = a * expf(1.0f - a);
    }
    __syncthreads();

    if (tid < T_DIM) {
        float acc = 0.0f;
        int mmax = tid < (K_FIR - 1) ? tid : (K_FIR - 1);
        for (int m = 1; m <= mmax; ++m)
            acc = fmaf(se[m], sz[tid - m], acc);
        u[(size_t)row * T_DIM + tid] = acc;
    }
}

// ---------------------------------------------------------------------------
// 5/8) Spike scan: exact fp32 recurrence, no FMA contraction.
//   y = A*(y + K*p); s = (u + y >= theta); p = A*p + s
// ---------------------------------------------------------------------------
__global__ void spike_kernel(const float* __restrict__ u, float* __restrict__ s,
                             int nrows) {
    int r = blockIdx.x * blockDim.x + threadIdx.x;
    if (r >= nrows) return;
    float p = 0.0f, y = 0.0f;
    size_t base = (size_t)r * T_DIM;
    for (int t = 0; t < T_DIM; ++t) {
        float ut = u[base + t];
        y = __fmul_rn(A_REF_F, __fadd_rn(y, __fmul_rn(K_REF_F, p)));
        float sp = (__fadd_rn(ut, y) >= THETA_F) ? 1.0f : 0.0f;
        p = __fadd_rn(__fmul_rn(A_REF_F, p), sp);
        s[base + t] = sp;
    }
}

// ---------------------------------------------------------------------------
// 6) Layer-2 GEMM: z2[n,o2,t] = sum_o w2[o2,o] * s1[n,o,t].
//    grid (8, 19), block 160 (= 10 o2 x 16 t). s1 tile + w2 in smem.
// ---------------------------------------------------------------------------
__global__ void g2_kernel(const float* __restrict__ w2) {
    __shared__ float sw[O2 * O1];        // 16.4 KB
    __shared__ float st[O1 * 17];        // 27.9 KB, pad stride 17
    int n  = blockIdx.x;
    int t0 = blockIdx.y * 16;
    int tid = threadIdx.x;               // 160

    for (int k = tid; k < O2 * O1; k += 160) sw[k] = w2[k];
    for (int k = tid; k < O1 * 16; k += 160) {
        int o = k / 16, tl = k % 16;
        int t = t0 + tl;
        st[o * 17 + tl] = (t < T_DIM)
            ? g_s1[((size_t)n * O1 + o) * T_DIM + t] : 0.0f;
    }
    __syncthreads();

    int tl = tid % 16, o2 = tid / 16;
    int t = t0 + tl;
    if (t < T_DIM) {
        float acc = 0.0f;
        for (int o = 0; o < O1; ++o)
            acc = fmaf(sw[o2 * O1 + o], st[o * 17 + tl], acc);
        g_z2[((size_t)n * O2 + o2) * T_DIM + t] = acc;
    }
}

// ---------------------------------------------------------------------------
extern "C" void kernel_launch(void* const* d_in, const int* in_sizes, int n_in,
                              void* d_out, int out_size) {
    const float* x  = (const float*)d_in[0];
    const float* w1 = (const float*)d_in[1];
    const float* w2 = (const float*)d_in[2];
    float* out = (float*)d_out;

    float *z1, *u1, *s1, *z2, *u2;
    cudaGetSymbolAddress((void**)&z1, g_z1);
    cudaGetSymbolAddress((void**)&u1, g_u1);
    cudaGetSymbolAddress((void**)&s1, g_s1);
    cudaGetSymbolAddress((void**)&z2, g_z2);
    cudaGetSymbolAddress((void**)&u2, g_u2);

    w1t_kernel<<<dim3(I_DIM / 32, (O1_PAD) / 32), dim3(32, 32)>>>(w1);
    compact_kernel<<<dim3(N_BATCH, 10), 256>>>(x);
    g1_kernel<<<NCOLS, 128>>>();
    psp_kernel<<<N_BATCH * O1, 320>>>(z1, u1);
    spike_kernel<<<(N_BATCH * O1 + 127) / 128, 128>>>(u1, s1, N_BATCH * O1);
    g2_kernel<<<dim3(N_BATCH, (T_DIM + 15) / 16), 160>>>(w2);
    psp_kernel<<<N_BATCH * O2, 320>>>(z2, u2);
    spike_kernel<<<1, 128>>>(u2, out, N_BATCH * O2);
}

// round 2
// speedup vs baseline: 1.9785x; 1.9785x over previous
#include <cuda_runtime.h>
#include <cuda_bf16.h>
#include <math.h>

// ---------------------------------------------------------------------------
// SLAYER SRM-alpha 2-layer SNN.  (see round-1 header for structure)
// Round 2: segmented parallel compaction (640 CTAs), g1 with 4 accumulators +
// unroll-8 MLP, smem-tiled coalesced spike scan, g1 placed at launch index 3
// for ncu capture.
// ---------------------------------------------------------------------------

#define N_BATCH 8
#define I_DIM   32768
#define O1      410
#define O1_PAD  416
#define O2      10
#define T_DIM   300
#define K_FIR   100
#define SEG_N   8
#define SEG_I   (I_DIM / SEG_N)     // 4096
#define SEGCAP  256                 // nnz/seg: mean 123, sigma 11
#define IDX_CAP (SEG_N * SEGCAP)    // 2048
#define NCOLS   (N_BATCH * T_DIM)

#define A_REF_F 0.36787944117144233f
#define K_REF_F -54.365636569180902f
#define THETA_F 10.0f

// --- scratch (device globals: allocation-free) ---
__device__ float          g_w1t[(size_t)I_DIM * O1_PAD];   // 54.5 MB
__device__ unsigned short g_idx[(size_t)NCOLS * IDX_CAP];  // 9.8 MB
__device__ int            g_cnt[NCOLS * SEG_N];
__device__ float          g_z1[(size_t)N_BATCH * O1 * T_DIM];
__device__ float          g_u1[(size_t)N_BATCH * O1 * T_DIM];
__device__ float          g_s1[(size_t)N_BATCH * O1 * T_DIM];
__device__ float          g_z2[(size_t)N_BATCH * O2 * T_DIM];
__device__ float          g_u2[(size_t)N_BATCH * O2 * T_DIM];

__global__ void noop_kernel() {}

// ---------------------------------------------------------------------------
// 1) w1 (O,I) -> w1t (I, O1_PAD)
// ---------------------------------------------------------------------------
__global__ void w1t_kernel(const float* __restrict__ w1) {
    __shared__ float tile[32][33];
    int i0 = blockIdx.x * 32;
    int o0 = blockIdx.y * 32;
    int tx = threadIdx.x, ty = threadIdx.y;
    int o_in = o0 + ty;
    tile[ty][tx] = (o_in < O1) ? w1[(size_t)o_in * I_DIM + i0 + tx] : 0.0f;
    __syncthreads();
    g_w1t[(size_t)(i0 + ty) * O1_PAD + o0 + tx] = tile[tx][ty];
}

// ---------------------------------------------------------------------------
// 2) Segmented ordered compaction. grid (8, 10, 8): n, t-block(32), i-segment.
//    Per-segment ascending-i uint16 lists, per-segment counts.
// ---------------------------------------------------------------------------
__global__ void compact_kernel(const float* __restrict__ x) {
    __shared__ float tile[128][33];
    int n   = blockIdx.x;
    int t0  = blockIdx.y * 32;
    int seg = blockIdx.z;
    int tid = threadIdx.x, wid = tid >> 5, lane = tid & 31;

    int base0 = 0, base1 = 0, base2 = 0, base3 = 0;
    int tld = t0 + lane;
    int ibase = seg * SEG_I;

    for (int c = 0; c < SEG_I / 128; ++c) {
        int i0 = ibase + c * 128;
        #pragma unroll
        for (int k = 0; k < 16; ++k) {
            int r = wid * 16 + k;
            tile[r][lane] = (tld < T_DIM)
                ? x[((size_t)n * I_DIM + i0 + r) * T_DIM + tld] : 0.0f;
        }
        __syncthreads();

        #pragma unroll
        for (int cc = 0; cc < 4; ++cc) {
            int tl = wid * 4 + cc;
            int tg = t0 + tl;
            if (tg < T_DIM) {
                int* basep = (cc == 0) ? &base0 : (cc == 1) ? &base1
                           : (cc == 2) ? &base2 : &base3;
                size_t obase = (size_t)(n * T_DIM + tg) * IDX_CAP
                             + (size_t)seg * SEGCAP;
                #pragma unroll
                for (int j = 0; j < 4; ++j) {
                    float v = tile[j * 32 + lane][tl];
                    unsigned b = __ballot_sync(0xffffffffu, v != 0.0f);
                    if (v != 0.0f) {
                        int pos = *basep + __popc(b & ((1u << lane) - 1u));
                        if (pos < SEGCAP)
                            g_idx[obase + pos] =
                                (unsigned short)(i0 + j * 32 + lane);
                    }
                    *basep += __popc(b);
                }
            }
        }
        __syncthreads();
    }

    if (lane == 0) {
        int tg0 = t0 + wid * 4;
        int cb = (n * T_DIM) * SEG_N + seg;
        if (tg0 + 0 < T_DIM) g_cnt[cb + (tg0 + 0) * SEG_N] = min(base0, SEGCAP);
        if (tg0 + 1 < T_DIM) g_cnt[cb + (tg0 + 1) * SEG_N] = min(base1, SEGCAP);
        if (tg0 + 2 < T_DIM) g_cnt[cb + (tg0 + 2) * SEG_N] = min(base2, SEGCAP);
        if (tg0 + 3 < T_DIM) g_cnt[cb + (tg0 + 3) * SEG_N] = min(base3, SEGCAP);
    }
}

// ---------------------------------------------------------------------------
// 3) Layer-1 gather-sum GEMM. CTA per (n,t) column.
//    4 independent accumulators, unroll 8 (8 LDG.128 in flight per thread).
// ---------------------------------------------------------------------------
__global__ void __launch_bounds__(128) g1_kernel() {
    int col = blockIdx.x;
    int n = col / T_DIM, t = col % T_DIM;
    int tid = threadIdx.x;

    __shared__ unsigned short sidx[IDX_CAP];
    __shared__ int soff[SEG_N + 1];

    if (tid == 0) {
        int acc = 0;
        #pragma unroll
        for (int s = 0; s < SEG_N; ++s) {
            soff[s] = acc;
            acc += g_cnt[col * SEG_N + s];
        }
        soff[SEG_N] = acc;
    }
    __syncthreads();

    #pragma unroll
    for (int s = 0; s < SEG_N; ++s) {
        int c = soff[s + 1] - soff[s];
        for (int k = tid; k < c; k += 128)
            sidx[soff[s] + k] = g_idx[(size_t)col * IDX_CAP + s * SEGCAP + k];
    }
    __syncthreads();
    int cnt = soff[SEG_N];

    if (tid < 104) {
        const float4* w4 = reinterpret_cast<const float4*>(g_w1t);
        float4 c0 = make_float4(0.f, 0.f, 0.f, 0.f);
        float4 c1 = make_float4(0.f, 0.f, 0.f, 0.f);
        float4 c2 = make_float4(0.f, 0.f, 0.f, 0.f);
        float4 c3 = make_float4(0.f, 0.f, 0.f, 0.f);
        int k = 0;
        #define ACC(C, A)                                   \
            C.x = __fmaf_rn(A.x, 1.0f, C.x);                \
            C.y = __fmaf_rn(A.y, 1.0f, C.y);                \
            C.z = __fmaf_rn(A.z, 1.0f, C.z);                \
            C.w = __fmaf_rn(A.w, 1.0f, C.w);
        for (; k + 8 <= cnt; k += 8) {
            float4 a0 = w4[(size_t)sidx[k + 0] * (O1_PAD / 4) + tid];
            float4 a1 = w4[(size_t)sidx[k + 1] * (O1_PAD / 4) + tid];
            float4 a2 = w4[(size_t)sidx[k + 2] * (O1_PAD / 4) + tid];
            float4 a3 = w4[(size_t)sidx[k + 3] * (O1_PAD / 4) + tid];
            float4 a4 = w4[(size_t)sidx[k + 4] * (O1_PAD / 4) + tid];
            float4 a5 = w4[(size_t)sidx[k + 5] * (O1_PAD / 4) + tid];
            float4 a6 = w4[(size_t)sidx[k + 6] * (O1_PAD / 4) + tid];
            float4 a7 = w4[(size_t)sidx[k + 7] * (O1_PAD / 4) + tid];
            ACC(c0, a0) ACC(c1, a1) ACC(c2, a2) ACC(c3, a3)
            ACC(c0, a4) ACC(c1, a5) ACC(c2, a6) ACC(c3, a7)
        }
        for (; k < cnt; ++k) {
            float4 a0 = w4[(size_t)sidx[k] * (O1_PAD / 4) + tid];
            ACC(c0, a0)
        }
        #undef ACC
        float4 r;
        r.x = (c0.x + c1.x) + (c2.x + c3.x);
        r.y = (c0.y + c1.y) + (c2.y + c3.y);
        r.z = (c0.z + c1.z) + (c2.z + c3.z);
        r.w = (c0.w + c1.w) + (c2.w + c3.w);

        int o0 = tid * 4;
        size_t zb = ((size_t)n * O1) * T_DIM + t;
        if (o0 + 0 < O1) g_z1[zb + (size_t)(o0 + 0) * T_DIM] = r.x;
        if (o0 + 1 < O1) g_z1[zb + (size_t)(o0 + 1) * T_DIM] = r.y;
        if (o0 + 2 < O1) g_z1[zb + (size_t)(o0 + 2) * T_DIM] = r.z;
        if (o0 + 3 < O1) g_z1[zb + (size_t)(o0 + 3) * T_DIM] = r.w;
    }
}

// ---------------------------------------------------------------------------
// 4/7) PSP: exact truncated 100-tap SRM-alpha FIR along t. CTA per row.
// ---------------------------------------------------------------------------
__global__ void psp_kernel(const float* __restrict__ z, float* __restrict__ u) {
    __shared__ float sz[T_DIM];
    __shared__ float se[K_FIR];
    int row = blockIdx.x;
    int tid = threadIdx.x;   // 320

    if (tid < T_DIM) sz[tid] = z[(size_t)row * T_DIM + tid];
    if (tid < K_FIR) {
        float a = (float)tid / 10.0f;
        se[tid] = a * expf(1.0f - a);
    }
    __syncthreads();

    if (tid < T_DIM) {
        float acc = 0.0f;
        int mmax = tid < (K_FIR - 1) ? tid : (K_FIR - 1);
        for (int m = 1; m <= mmax; ++m)
            acc = fmaf(se[m], sz[tid - m], acc);
        u[(size_t)row * T_DIM + tid] = acc;
    }
}

// ---------------------------------------------------------------------------
// 5/8) Spike scan, smem-tiled for coalescing. 128 rows per CTA, 32-t chunks.
//   y = A*(y + K*p); s = (u + y >= theta); p = A*p + s   (exact fp32, no FMA)
// ---------------------------------------------------------------------------
__global__ void __launch_bounds__(128) spike_kernel(
        const float* __restrict__ u, float* __restrict__ s, int nrows) {
    __shared__ float tu[128][33];
    int r0  = blockIdx.x * 128;
    int tid = threadIdx.x;
    int wid = tid >> 5, lane = tid & 31;

    float p = 0.0f, y = 0.0f;
    bool valid = (r0 + tid) < nrows;

    for (int t0 = 0; t0 < T_DIM; t0 += 32) {
        int tw = T_DIM - t0 < 32 ? T_DIM - t0 : 32;
        // coalesced load: warp w loads rows [w*32, w*32+32), lane = t offset
        #pragma unroll 8
        for (int rr = 0; rr < 32; ++rr) {
            int r = r0 + wid * 32 + rr;
            tu[wid * 32 + rr][lane] = (r < nrows && lane < tw)
                ? u[(size_t)r * T_DIM + t0 + lane] : 0.0f;
        }
        __syncthreads();

        if (valid) {
            #pragma unroll
            for (int tt = 0; tt < 32; ++tt) {
                if (tt < tw) {
                    float ut = tu[tid][tt];
                    y = __fmul_rn(A_REF_F, __fadd_rn(y, __fmul_rn(K_REF_F, p)));
                    float sp = (__fadd_rn(ut, y) >= THETA_F) ? 1.0f : 0.0f;
                    p = __fadd_rn(__fmul_rn(A_REF_F, p), sp);
                    tu[tid][tt] = sp;
                }
            }
        }
        __syncthreads();

        #pragma unroll 8
        for (int rr = 0; rr < 32; ++rr) {
            int r = r0 + wid * 32 + rr;
            if (r < nrows && lane < tw)
                s[(size_t)r * T_DIM + t0 + lane] = tu[wid * 32 + rr][lane];
        }
        __syncthreads();
    }
}

// ---------------------------------------------------------------------------
// 6) Layer-2 GEMM: z2[n,o2,t] = sum_o w2[o2,o] * s1[n,o,t].
// ---------------------------------------------------------------------------
__global__ void g2_kernel(const float* __restrict__ w2) {
    __shared__ float sw[O2 * O1];
    __shared__ float st[O1 * 17];
    int n  = blockIdx.x;
    int t0 = blockIdx.y * 16;
    int tid = threadIdx.x;   // 160

    for (int k = tid; k < O2 * O1; k += 160) sw[k] = w2[k];
    for (int k = tid; k < O1 * 16; k += 160) {
        int o = k / 16, tl = k % 16;
        int t = t0 + tl;
        st[o * 17 + tl] = (t < T_DIM)
            ? g_s1[((size_t)n * O1 + o) * T_DIM + t] : 0.0f;
    }
    __syncthreads();

    int tl = tid % 16, o2 = tid / 16;
    int t = t0 + tl;
    if (t < T_DIM) {
        float acc = 0.0f;
        for (int o = 0; o < O1; ++o)
            acc = fmaf(sw[o2 * O1 + o], st[o * 17 + tl], acc);
        g_z2[((size_t)n * O2 + o2) * T_DIM + t] = acc;
    }
}

// ---------------------------------------------------------------------------
extern "C" void kernel_launch(void* const* d_in, const int* in_sizes, int n_in,
                              void* d_out, int out_size) {
    const float* x  = (const float*)d_in[0];
    const float* w1 = (const float*)d_in[1];
    const float* w2 = (const float*)d_in[2];
    float* out = (float*)d_out;

    float *z1, *u1, *s1, *z2, *u2;
    cudaGetSymbolAddress((void**)&z1, g_z1);
    cudaGetSymbolAddress((void**)&u1, g_u1);
    cudaGetSymbolAddress((void**)&s1, g_s1);
    cudaGetSymbolAddress((void**)&z2, g_z2);
    cudaGetSymbolAddress((void**)&u2, g_u2);

    w1t_kernel<<<dim3(I_DIM / 32, O1_PAD / 32), dim3(32, 32)>>>(w1);     // 0
    compact_kernel<<<dim3(N_BATCH, 10, SEG_N), 256>>>(x);                // 1
    noop_kernel<<<1, 32>>>();                                            // 2
    g1_kernel<<<NCOLS, 128>>>();                                         // 3 (ncu)
    psp_kernel<<<N_BATCH * O1, 320>>>(z1, u1);                           // 4
    spike_kernel<<<(N_BATCH * O1 + 127) / 128, 128>>>(u1, s1, N_BATCH * O1);
    g2_kernel<<<dim3(N_BATCH, (T_DIM + 15) / 16), 160>>>(w2);
    psp_kernel<<<N_BATCH * O2, 320>>>(z2, u2);
    spike_kernel<<<1, 128>>>(u2, out, N_BATCH * O2);
}

// round 3
// speedup vs baseline: 2.0048x; 1.0133x over previous
#include <cuda_runtime.h>
#include <cuda_bf16.h>
#include <math.h>

// ---------------------------------------------------------------------------
// SLAYER SRM-alpha 2-layer SNN.
// Round 3: g1 split-K x4 across CTAs (reduce fused into psp), compact with
// 16 i-segments, warp-scan segment offsets in g1.
// ---------------------------------------------------------------------------

#define N_BATCH 8
#define I_DIM   32768
#define O1      410
#define O1_PAD  416
#define O2      10
#define T_DIM   300
#define K_FIR   100
#define SEG_N   16
#define SEG_I   (I_DIM / SEG_N)     // 2048
#define SEGCAP  128                 // nnz/seg: mean 61.4, sigma 7.7 (cap=8.6σ)
#define IDX_CAP (SEG_N * SEGCAP)    // 2048
#define NCOLS   (N_BATCH * T_DIM)
#define SPLIT   4

#define A_REF_F 0.36787944117144233f
#define K_REF_F -54.365636569180902f
#define THETA_F 10.0f

// --- scratch (device globals: allocation-free) ---
__device__ float          g_w1t[(size_t)I_DIM * O1_PAD];           // 54.5 MB
__device__ unsigned short g_idx[(size_t)NCOLS * IDX_CAP];          // 9.8 MB
__device__ int            g_cnt[NCOLS * SEG_N];
__device__ float          g_z1p[(size_t)SPLIT * N_BATCH * O1 * T_DIM]; // 15.7 MB
__device__ float          g_u1[(size_t)N_BATCH * O1 * T_DIM];
__device__ float          g_s1[(size_t)N_BATCH * O1 * T_DIM];
__device__ float          g_z2[(size_t)N_BATCH * O2 * T_DIM];
__device__ float          g_u2[(size_t)N_BATCH * O2 * T_DIM];

__global__ void noop_kernel() {}

// ---------------------------------------------------------------------------
// 1) w1 (O,I) -> w1t (I, O1_PAD)
// ---------------------------------------------------------------------------
__global__ void w1t_kernel(const float* __restrict__ w1) {
    __shared__ float tile[32][33];
    int i0 = blockIdx.x * 32;
    int o0 = blockIdx.y * 32;
    int tx = threadIdx.x, ty = threadIdx.y;
    int o_in = o0 + ty;
    tile[ty][tx] = (o_in < O1) ? w1[(size_t)o_in * I_DIM + i0 + tx] : 0.0f;
    __syncthreads();
    g_w1t[(size_t)(i0 + ty) * O1_PAD + o0 + tx] = tile[tx][ty];
}

// ---------------------------------------------------------------------------
// 2) Segmented ordered compaction. grid (8, 10, 16): n, t-block(32), i-seg.
// ---------------------------------------------------------------------------
__global__ void compact_kernel(const float* __restrict__ x) {
    __shared__ float tile[128][33];
    int n   = blockIdx.x;
    int t0  = blockIdx.y * 32;
    int seg = blockIdx.z;
    int tid = threadIdx.x, wid = tid >> 5, lane = tid & 31;

    int base0 = 0, base1 = 0, base2 = 0, base3 = 0;
    int tld = t0 + lane;
    int ibase = seg * SEG_I;

    for (int c = 0; c < SEG_I / 128; ++c) {
        int i0 = ibase + c * 128;
        #pragma unroll
        for (int k = 0; k < 16; ++k) {
            int r = wid * 16 + k;
            tile[r][lane] = (tld < T_DIM)
                ? x[((size_t)n * I_DIM + i0 + r) * T_DIM + tld] : 0.0f;
        }
        __syncthreads();

        #pragma unroll
        for (int cc = 0; cc < 4; ++cc) {
            int tl = wid * 4 + cc;
            int tg = t0 + tl;
            if (tg < T_DIM) {
                int* basep = (cc == 0) ? &base0 : (cc == 1) ? &base1
                           : (cc == 2) ? &base2 : &base3;
                size_t obase = (size_t)(n * T_DIM + tg) * IDX_CAP
                             + (size_t)seg * SEGCAP;
                #pragma unroll
                for (int j = 0; j < 4; ++j) {
                    float v = tile[j * 32 + lane][tl];
                    unsigned b = __ballot_sync(0xffffffffu, v != 0.0f);
                    if (v != 0.0f) {
                        int pos = *basep + __popc(b & ((1u << lane) - 1u));
                        if (pos < SEGCAP)
                            g_idx[obase + pos] =
                                (unsigned short)(i0 + j * 32 + lane);
                    }
                    *basep += __popc(b);
                }
            }
        }
        __syncthreads();
    }

    if (lane == 0) {
        int tg0 = t0 + wid * 4;
        int cb = (n * T_DIM) * SEG_N + seg;
        if (tg0 + 0 < T_DIM) g_cnt[cb + (tg0 + 0) * SEG_N] = min(base0, SEGCAP);
        if (tg0 + 1 < T_DIM) g_cnt[cb + (tg0 + 1) * SEG_N] = min(base1, SEGCAP);
        if (tg0 + 2 < T_DIM) g_cnt[cb + (tg0 + 2) * SEG_N] = min(base2, SEGCAP);
        if (tg0 + 3 < T_DIM) g_cnt[cb + (tg0 + 3) * SEG_N] = min(base3, SEGCAP);
    }
}

// ---------------------------------------------------------------------------
// 3) Layer-1 gather-sum GEMM, split-K x4. grid (2400, 4).
//    CTA (col, q) sums indices [q*cnt/4, (q+1)*cnt/4) -> g_z1p[q].
// ---------------------------------------------------------------------------
__global__ void __launch_bounds__(128) g1_kernel() {
    int col = blockIdx.x;
    int q   = blockIdx.y;
    int n = col / T_DIM, t = col % T_DIM;
    int tid = threadIdx.x;

    __shared__ unsigned short sidx[IDX_CAP];
    __shared__ int soff[SEG_N + 1];

    if (tid < 32) {
        int lane = tid;
        int c = (lane < SEG_N) ? g_cnt[col * SEG_N + lane] : 0;
        #pragma unroll
        for (int d = 1; d < 32; d <<= 1) {
            int v = __shfl_up_sync(0xffffffffu, c, d);
            if (lane >= d) c += v;
        }
        if (lane < SEG_N) soff[lane + 1] = c;
        if (lane == 0)    soff[0] = 0;
    }
    __syncthreads();

    int cnt = soff[SEG_N];
    int k0 = (cnt * q) / SPLIT;
    int k1 = (cnt * (q + 1)) / SPLIT;

    // load only segments overlapping [k0, k1)
    #pragma unroll
    for (int s = 0; s < SEG_N; ++s) {
        int b = soff[s], e = soff[s + 1];
        if (e <= k0 || b >= k1) continue;
        int c = e - b;
        for (int k = tid; k < c; k += 128)
            sidx[b + k] = g_idx[(size_t)col * IDX_CAP + s * SEGCAP + k];
    }
    __syncthreads();

    if (tid < 104) {
        const float4* w4 = reinterpret_cast<const float4*>(g_w1t);
        float4 c0 = make_float4(0.f, 0.f, 0.f, 0.f);
        float4 c1 = make_float4(0.f, 0.f, 0.f, 0.f);
        float4 c2 = make_float4(0.f, 0.f, 0.f, 0.f);
        float4 c3 = make_float4(0.f, 0.f, 0.f, 0.f);
        int k = k0;
        #define ACC(C, A)                                   \
            C.x = __fmaf_rn(A.x, 1.0f, C.x);                \
            C.y = __fmaf_rn(A.y, 1.0f, C.y);                \
            C.z = __fmaf_rn(A.z, 1.0f, C.z);                \
            C.w = __fmaf_rn(A.w, 1.0f, C.w);
        for (; k + 8 <= k1; k += 8) {
            float4 a0 = w4[(size_t)sidx[k + 0] * (O1_PAD / 4) + tid];
            float4 a1 = w4[(size_t)sidx[k + 1] * (O1_PAD / 4) + tid];
            float4 a2 = w4[(size_t)sidx[k + 2] * (O1_PAD / 4) + tid];
            float4 a3 = w4[(size_t)sidx[k + 3] * (O1_PAD / 4) + tid];
            float4 a4 = w4[(size_t)sidx[k + 4] * (O1_PAD / 4) + tid];
            float4 a5 = w4[(size_t)sidx[k + 5] * (O1_PAD / 4) + tid];
            float4 a6 = w4[(size_t)sidx[k + 6] * (O1_PAD / 4) + tid];
            float4 a7 = w4[(size_t)sidx[k + 7] * (O1_PAD / 4) + tid];
            ACC(c0, a0) ACC(c1, a1) ACC(c2, a2) ACC(c3, a3)
            ACC(c0, a4) ACC(c1, a5) ACC(c2, a6) ACC(c3, a7)
        }
        for (; k < k1; ++k) {
            float4 a0 = w4[(size_t)sidx[k] * (O1_PAD / 4) + tid];
            ACC(c0, a0)
        }
        #undef ACC
        float4 r;
        r.x = (c0.x + c1.x) + (c2.x + c3.x);
        r.y = (c0.y + c1.y) + (c2.y + c3.y);
        r.z = (c0.z + c1.z) + (c2.z + c3.z);
        r.w = (c0.w + c1.w) + (c2.w + c3.w);

        int o0 = tid * 4;
        size_t zb = (size_t)q * (N_BATCH * O1 * T_DIM)
                  + ((size_t)n * O1) * T_DIM + t;
        if (o0 + 0 < O1) g_z1p[zb + (size_t)(o0 + 0) * T_DIM] = r.x;
        if (o0 + 1 < O1) g_z1p[zb + (size_t)(o0 + 1) * T_DIM] = r.y;
        if (o0 + 2 < O1) g_z1p[zb + (size_t)(o0 + 2) * T_DIM] = r.z;
        if (o0 + 3 < O1) g_z1p[zb + (size_t)(o0 + 3) * T_DIM] = r.w;
    }
}

// ---------------------------------------------------------------------------
// 4) Layer-1 PSP with fused 4-way split reduce. CTA per (n,o) row.
// ---------------------------------------------------------------------------
__global__ void psp4_kernel() {
    __shared__ float sz[T_DIM];
    __shared__ float se[K_FIR];
    int row = blockIdx.x;
    int tid = threadIdx.x;   // 320
    const size_t PS = (size_t)N_BATCH * O1 * T_DIM;

    if (tid < T_DIM) {
        size_t idx = (size_t)row * T_DIM + tid;
        sz[tid] = (g_z1p[idx] + g_z1p[idx + PS])
                + (g_z1p[idx + 2 * PS] + g_z1p[idx + 3 * PS]);
    }
    if (tid < K_FIR) {
        float a = (float)tid / 10.0f;
        se[tid] = a * expf(1.0f - a);
    }
    __syncthreads();

    if (tid < T_DIM) {
        float acc = 0.0f;
        int mmax = tid < (K_FIR - 1) ? tid : (K_FIR - 1);
        for (int m = 1; m <= mmax; ++m)
            acc = fmaf(se[m], sz[tid - m], acc);
        g_u1[(size_t)row * T_DIM + tid] = acc;
    }
}

// ---------------------------------------------------------------------------
// 7) Layer-2 PSP (plain).
// ---------------------------------------------------------------------------
__global__ void psp_kernel(const float* __restrict__ z, float* __restrict__ u) {
    __shared__ float sz[T_DIM];
    __shared__ float se[K_FIR];
    int row = blockIdx.x;
    int tid = threadIdx.x;

    if (tid < T_DIM) sz[tid] = z[(size_t)row * T_DIM + tid];
    if (tid < K_FIR) {
        float a = (float)tid / 10.0f;
        se[tid] = a * expf(1.0f - a);
    }
    __syncthreads();

    if (tid < T_DIM) {
        float acc = 0.0f;
        int mmax = tid < (K_FIR - 1) ? tid : (K_FIR - 1);
        for (int m = 1; m <= mmax; ++m)
            acc = fmaf(se[m], sz[tid - m], acc);
        u[(size_t)row * T_DIM + tid] = acc;
    }
}

// ---------------------------------------------------------------------------
// 5/8) Spike scan, smem-tiled. Exact fp32 recurrence, no FMA contraction.
// ---------------------------------------------------------------------------
__global__ void __launch_bounds__(128) spike_kernel(
        const float* __restrict__ u, float* __restrict__ s, int nrows) {
    __shared__ float tu[128][33];
    int r0  = blockIdx.x * 128;
    int tid = threadIdx.x;
    int wid = tid >> 5, lane = tid & 31;

    float p = 0.0f, y = 0.0f;
    bool valid = (r0 + tid) < nrows;

    for (int t0 = 0; t0 < T_DIM; t0 += 32) {
        int tw = T_DIM - t0 < 32 ? T_DIM - t0 : 32;
        #pragma unroll 8
        for (int rr = 0; rr < 32; ++rr) {
            int r = r0 + wid * 32 + rr;
            tu[wid * 32 + rr][lane] = (r < nrows && lane < tw)
                ? u[(size_t)r * T_DIM + t0 + lane] : 0.0f;
        }
        __syncthreads();

        if (valid) {
            #pragma unroll
            for (int tt = 0; tt < 32; ++tt) {
                if (tt < tw) {
                    float ut = tu[tid][tt];
                    y = __fmul_rn(A_REF_F, __fadd_rn(y, __fmul_rn(K_REF_F, p)));
                    float sp = (__fadd_rn(ut, y) >= THETA_F) ? 1.0f : 0.0f;
                    p = __fadd_rn(__fmul_rn(A_REF_F, p), sp);
                    tu[tid][tt] = sp;
                }
            }
        }
        __syncthreads();

        #pragma unroll 8
        for (int rr = 0; rr < 32; ++rr) {
            int r = r0 + wid * 32 + rr;
            if (r < nrows && lane < tw)
                s[(size_t)r * T_DIM + t0 + lane] = tu[wid * 32 + rr][lane];
        }
        __syncthreads();
    }
}

// ---------------------------------------------------------------------------
// 6) Layer-2 GEMM: z2[n,o2,t] = sum_o w2[o2,o] * s1[n,o,t].
// ---------------------------------------------------------------------------
__global__ void g2_kernel(const float* __restrict__ w2) {
    __shared__ float sw[O2 * O1];
    __shared__ float st[O1 * 17];
    int n  = blockIdx.x;
    int t0 = blockIdx.y * 16;
    int tid = threadIdx.x;   // 160

    for (int k = tid; k < O2 * O1; k += 160) sw[k] = w2[k];
    for (int k = tid; k < O1 * 16; k += 160) {
        int o = k / 16, tl = k % 16;
        int t = t0 + tl;
        st[o * 17 + tl] = (t < T_DIM)
            ? g_s1[((size_t)n * O1 + o) * T_DIM + t] : 0.0f;
    }
    __syncthreads();

    int tl = tid % 16, o2 = tid / 16;
    int t = t0 + tl;
    if (t < T_DIM) {
        float acc = 0.0f;
        for (int o = 0; o < O1; ++o)
            acc = fmaf(sw[o2 * O1 + o], st[o * 17 + tl], acc);
        g_z2[((size_t)n * O2 + o2) * T_DIM + t] = acc;
    }
}

// ---------------------------------------------------------------------------
extern "C" void kernel_launch(void* const* d_in, const int* in_sizes, int n_in,
                              void* d_out, int out_size) {
    const float* x  = (const float*)d_in[0];
    const float* w1 = (const float*)d_in[1];
    const float* w2 = (const float*)d_in[2];
    float* out = (float*)d_out;

    float *u1, *s1, *z2, *u2;
    cudaGetSymbolAddress((void**)&u1, g_u1);
    cudaGetSymbolAddress((void**)&s1, g_s1);
    cudaGetSymbolAddress((void**)&z2, g_z2);
    cudaGetSymbolAddress((void**)&u2, g_u2);

    w1t_kernel<<<dim3(I_DIM / 32, O1_PAD / 32), dim3(32, 32)>>>(w1);     // 0
    compact_kernel<<<dim3(N_BATCH, 10, SEG_N), 256>>>(x);                // 1
    noop_kernel<<<1, 32>>>();                                            // 2
    g1_kernel<<<dim3(NCOLS, SPLIT), 128>>>();                            // 3 (ncu)
    psp4_kernel<<<N_BATCH * O1, 320>>>();                                // 4
    spike_kernel<<<(N_BATCH * O1 + 127) / 128, 128>>>(u1, s1, N_BATCH * O1);
    g2_kernel<<<dim3(N_BATCH, (T_DIM + 15) / 16), 160>>>(w2);
    psp_kernel<<<N_BATCH * O2, 320>>>(z2, u2);
    spike_kernel<<<1, 128>>>(u2, out, N_BATCH * O2);
}

// round 4
// speedup vs baseline: 2.3385x; 1.1665x over previous
#include <cuda_runtime.h>
#include <cuda_bf16.h>
#include <math.h>

// ---------------------------------------------------------------------------
// SLAYER SRM-alpha 2-layer SNN.
// Round 4: fused pre_kernel (w1t transpose || segmented compaction with
// float4 loads + precomputed byte offsets), g1 with vectorized offset fetch
// and IADD addressing, 4-chain PSP FIR.
// ---------------------------------------------------------------------------

#define N_BATCH 8
#define I_DIM   32768
#define O1      410
#define O1_PAD  416
#define ROW_B   (O1_PAD * 4)        // 1664 bytes per w1t row
#define O2      10
#define T_DIM   300
#define K_FIR   100
#define SEG_N   16
#define SEG_I   (I_DIM / SEG_N)     // 2048
#define SEGCAP  128
#define IDX_CAP (SEG_N * SEGCAP)    // 2048
#define NCOLS   (N_BATCH * T_DIM)
#define SPLIT   4

#define CPT_CTAS 1280               // 8 * 10 * 16
#define W1T_CTAS (1024 * 13)        // (I/32) * (O1_PAD/32)

#define A_REF_F 0.36787944117144233f
#define K_REF_F -54.365636569180902f
#define THETA_F 10.0f

// --- scratch (device globals: allocation-free) ---
__device__ float        g_w1t[(size_t)I_DIM * O1_PAD];            // 54.5 MB
__device__ unsigned int g_idx[(size_t)NCOLS * IDX_CAP];           // 19.7 MB (byte offsets)
__device__ int          g_cnt[NCOLS * SEG_N];
__device__ float        g_z1p[(size_t)SPLIT * N_BATCH * O1 * T_DIM];
__device__ float        g_u1[(size_t)N_BATCH * O1 * T_DIM];
__device__ float        g_s1[(size_t)N_BATCH * O1 * T_DIM];
__device__ float        g_z2[(size_t)N_BATCH * O2 * T_DIM];
__device__ float        g_u2[(size_t)N_BATCH * O2 * T_DIM];

__global__ void noop_kernel() {}

// ---------------------------------------------------------------------------
// 0) Fused preprocessing: blocks [0, CPT_CTAS) do segmented compaction,
//    blocks [CPT_CTAS, CPT_CTAS+W1T_CTAS) do the w1 transpose. 256 threads.
// ---------------------------------------------------------------------------
__global__ void __launch_bounds__(256) pre_kernel(
        const float* __restrict__ x, const float* __restrict__ w1) {
    __shared__ float tile[128][33];
    int tid = threadIdx.x, wid = tid >> 5, lane = tid & 31;

    if (blockIdx.x >= CPT_CTAS) {
        // ---- w1 (O,I) -> w1t (I, O1_PAD) transpose, 32x32 tile ----
        int t_  = blockIdx.x - CPT_CTAS;
        int i0 = (t_ & 1023) * 32;          // 1024 i-tiles
        int o0 = (t_ >> 10) * 32;           // 13 o-tiles
        #pragma unroll
        for (int k = 0; k < 4; ++k) {
            int oy = wid * 4 + k;
            int o = o0 + oy;
            tile[oy][lane] = (o < O1) ? w1[(size_t)o * I_DIM + i0 + lane] : 0.0f;
        }
        __syncthreads();
        #pragma unroll
        for (int k = 0; k < 4; ++k) {
            int iy = wid * 4 + k;
            g_w1t[(size_t)(i0 + iy) * O1_PAD + o0 + lane] = tile[lane][iy];
        }
        return;
    }

    // ---- segmented ordered compaction ----
    int b   = blockIdx.x;
    int n   = b / 160;
    int rem = b % 160;
    int t0  = (rem / 16) * 32;
    int seg = rem % 16;

    int base0 = 0, base1 = 0, base2 = 0, base3 = 0;
    int ibase = seg * SEG_I;
    bool full = (t0 + 32 <= T_DIM);

    for (int c = 0; c < SEG_I / 128; ++c) {
        int i0 = ibase + c * 128;
        if (full) {
            // float4 loads: 1024 float4 per chunk, 4 per thread
            #pragma unroll
            for (int it = 0; it < 4; ++it) {
                int idx = it * 256 + tid;
                int r = idx >> 3;          // 0..127
                int q = idx & 7;           // t-quad 0..7
                float4 v = *reinterpret_cast<const float4*>(
                    &x[((size_t)n * I_DIM + i0 + r) * T_DIM + t0 + q * 4]);
                tile[r][q * 4 + 0] = v.x;
                tile[r][q * 4 + 1] = v.y;
                tile[r][q * 4 + 2] = v.z;
                tile[r][q * 4 + 3] = v.w;
            }
        } else {
            int tld = t0 + lane;
            #pragma unroll
            for (int k = 0; k < 16; ++k) {
                int r = (tid >> 5) * 16 + k;
                tile[r][lane] = (tld < T_DIM)
                    ? x[((size_t)n * I_DIM + i0 + r) * T_DIM + tld] : 0.0f;
            }
        }
        __syncthreads();

        #pragma unroll
        for (int cc = 0; cc < 4; ++cc) {
            int tl = wid * 4 + cc;
            int tg = t0 + tl;
            if (tg < T_DIM) {
                int* basep = (cc == 0) ? &base0 : (cc == 1) ? &base1
                           : (cc == 2) ? &base2 : &base3;
                size_t obase = (size_t)(n * T_DIM + tg) * IDX_CAP
                             + (size_t)seg * SEGCAP;
                #pragma unroll
                for (int j = 0; j < 4; ++j) {
                    float v = tile[j * 32 + lane][tl];
                    unsigned bm = __ballot_sync(0xffffffffu, v != 0.0f);
                    if (v != 0.0f) {
                        int pos = *basep + __popc(bm & ((1u << lane) - 1u));
                        if (pos < SEGCAP)
                            g_idx[obase + pos] =
                                (unsigned int)(i0 + j * 32 + lane) * ROW_B;
                    }
                    *basep += __popc(bm);
                }
            }
        }
        __syncthreads();
    }

    if (lane == 0) {
        int tg0 = t0 + wid * 4;
        int cb = (n * T_DIM) * SEG_N + seg;
        if (tg0 + 0 < T_DIM) g_cnt[cb + (tg0 + 0) * SEG_N] = min(base0, SEGCAP);
        if (tg0 + 1 < T_DIM) g_cnt[cb + (tg0 + 1) * SEG_N] = min(base1, SEGCAP);
        if (tg0 + 2 < T_DIM) g_cnt[cb + (tg0 + 2) * SEG_N] = min(base2, SEGCAP);
        if (tg0 + 3 < T_DIM) g_cnt[cb + (tg0 + 3) * SEG_N] = min(base3, SEGCAP);
    }
}

// ---------------------------------------------------------------------------
// 3) Layer-1 gather-sum GEMM, split-K x4, precomputed byte offsets.
// ---------------------------------------------------------------------------
__global__ void __launch_bounds__(128) g1_kernel() {
    int col = blockIdx.x;
    int q   = blockIdx.y;
    int n = col / T_DIM, t = col % T_DIM;
    int tid = threadIdx.x;

    __shared__ unsigned int sofs[640];     // split range rebased to 0 (aligned)
    __shared__ int soff[SEG_N + 1];

    if (tid < 32) {
        int lane = tid;
        int c = (lane < SEG_N) ? g_cnt[col * SEG_N + lane] : 0;
        #pragma unroll
        for (int d = 1; d < 32; d <<= 1) {
            int v = __shfl_up_sync(0xffffffffu, c, d);
            if (lane >= d) c += v;
        }
        if (lane < SEG_N) soff[lane + 1] = c;
        if (lane == 0)    soff[0] = 0;
    }
    __syncthreads();

    int cnt = soff[SEG_N];
    int k0 = (cnt * q) / SPLIT;
    int k1 = (cnt * (q + 1)) / SPLIT;
    int M  = k1 - k0;

    #pragma unroll
    for (int s = 0; s < SEG_N; ++s) {
        int sb = soff[s], se_ = soff[s + 1];
        int lo = sb > k0 ? sb : k0;
        int hi = se_ < k1 ? se_ : k1;
        for (int k = lo + tid; k < hi; k += 128)
            sofs[k - k0] = g_idx[(size_t)col * IDX_CAP + s * SEGCAP + (k - sb)];
    }
    __syncthreads();

    if (tid < 104) {
        const char* wbase = reinterpret_cast<const char*>(g_w1t)
                          + (size_t)tid * 16;
        float4 c0 = make_float4(0.f, 0.f, 0.f, 0.f);
        float4 c1 = make_float4(0.f, 0.f, 0.f, 0.f);
        float4 c2 = make_float4(0.f, 0.f, 0.f, 0.f);
        float4 c3 = make_float4(0.f, 0.f, 0.f, 0.f);
        #define ACC(C, A)                                   \
            C.x = __fmaf_rn(A.x, 1.0f, C.x);                \
            C.y = __fmaf_rn(A.y, 1.0f, C.y);                \
            C.z = __fmaf_rn(A.z, 1.0f, C.z);                \
            C.w = __fmaf_rn(A.w, 1.0f, C.w);
        int m = 0;
        for (; m + 8 <= M; m += 8) {
            uint4 o0 = *reinterpret_cast<const uint4*>(&sofs[m]);
            uint4 o1 = *reinterpret_cast<const uint4*>(&sofs[m + 4]);
            float4 a0 = *reinterpret_cast<const float4*>(wbase + o0.x);
            float4 a1 = *reinterpret_cast<const float4*>(wbase + o0.y);
            float4 a2 = *reinterpret_cast<const float4*>(wbase + o0.z);
            float4 a3 = *reinterpret_cast<const float4*>(wbase + o0.w);
            float4 a4 = *reinterpret_cast<const float4*>(wbase + o1.x);
            float4 a5 = *reinterpret_cast<const float4*>(wbase + o1.y);
            float4 a6 = *reinterpret_cast<const float4*>(wbase + o1.z);
            float4 a7 = *reinterpret_cast<const float4*>(wbase + o1.w);
            ACC(c0, a0) ACC(c1, a1) ACC(c2, a2) ACC(c3, a3)
            ACC(c0, a4) ACC(c1, a5) ACC(c2, a6) ACC(c3, a7)
        }
        for (; m < M; ++m) {
            float4 a0 = *reinterpret_cast<const float4*>(wbase + sofs[m]);
            ACC(c0, a0)
        }
        #undef ACC
        float4 r;
        r.x = (c0.x + c1.x) + (c2.x + c3.x);
        r.y = (c0.y + c1.y) + (c2.y + c3.y);
        r.z = (c0.z + c1.z) + (c2.z + c3.z);
        r.w = (c0.w + c1.w) + (c2.w + c3.w);

        int o0i = tid * 4;
        size_t zb = (size_t)q * ((size_t)N_BATCH * O1 * T_DIM)
                  + ((size_t)n * O1) * T_DIM + t;
        if (o0i + 0 < O1) g_z1p[zb + (size_t)(o0i + 0) * T_DIM] = r.x;
        if (o0i + 1 < O1) g_z1p[zb + (size_t)(o0i + 1) * T_DIM] = r.y;
        if (o0i + 2 < O1) g_z1p[zb + (size_t)(o0i + 2) * T_DIM] = r.z;
        if (o0i + 3 < O1) g_z1p[zb + (size_t)(o0i + 3) * T_DIM] = r.w;
    }
}

// ---------------------------------------------------------------------------
// 4) Layer-1 PSP with fused 4-way split reduce; 4 FIR accumulation chains.
// ---------------------------------------------------------------------------
__global__ void psp4_kernel() {
    __shared__ float sz[T_DIM];
    __shared__ float se[K_FIR];
    int row = blockIdx.x;
    int tid = threadIdx.x;   // 320
    const size_t PS = (size_t)N_BATCH * O1 * T_DIM;

    if (tid < T_DIM) {
        size_t idx = (size_t)row * T_DIM + tid;
        sz[tid] = (g_z1p[idx] + g_z1p[idx + PS])
                + (g_z1p[idx + 2 * PS] + g_z1p[idx + 3 * PS]);
    }
    if (tid < K_FIR) {
        float a = (float)tid / 10.0f;
        se[tid] = a * expf(1.0f - a);
    }
    __syncthreads();

    if (tid < T_DIM) {
        int mmax = tid < (K_FIR - 1) ? tid : (K_FIR - 1);
        float a0 = 0.f, a1 = 0.f, a2 = 0.f, a3 = 0.f;
        int m = 1;
        for (; m + 3 <= mmax; m += 4) {
            a0 = fmaf(se[m + 0], sz[tid - m - 0], a0);
            a1 = fmaf(se[m + 1], sz[tid - m - 1], a1);
            a2 = fmaf(se[m + 2], sz[tid - m - 2], a2);
            a3 = fmaf(se[m + 3], sz[tid - m - 3], a3);
        }
        for (; m <= mmax; ++m) a0 = fmaf(se[m], sz[tid - m], a0);
        g_u1[(size_t)row * T_DIM + tid] = (a0 + a1) + (a2 + a3);
    }
}

// ---------------------------------------------------------------------------
// 7) Layer-2 PSP (plain, 4-chain).
// ---------------------------------------------------------------------------
__global__ void psp_kernel(const float* __restrict__ z, float* __restrict__ u) {
    __shared__ float sz[T_DIM];
    __shared__ float se[K_FIR];
    int row = blockIdx.x;
    int tid = threadIdx.x;

    if (tid < T_DIM) sz[tid] = z[(size_t)row * T_DIM + tid];
    if (tid < K_FIR) {
        float a = (float)tid / 10.0f;
        se[tid] = a * expf(1.0f - a);
    }
    __syncthreads();

    if (tid < T_DIM) {
        int mmax = tid < (K_FIR - 1) ? tid : (K_FIR - 1);
        float a0 = 0.f, a1 = 0.f, a2 = 0.f, a3 = 0.f;
        int m = 1;
        for (; m + 3 <= mmax; m += 4) {
            a0 = fmaf(se[m + 0], sz[tid - m - 0], a0);
            a1 = fmaf(se[m + 1], sz[tid - m - 1], a1);
            a2 = fmaf(se[m + 2], sz[tid - m - 2], a2);
            a3 = fmaf(se[m + 3], sz[tid - m - 3], a3);
        }
        for (; m <= mmax; ++m) a0 = fmaf(se[m], sz[tid - m], a0);
        u[(size_t)row * T_DIM + tid] = (a0 + a1) + (a2 + a3);
    }
}

// ---------------------------------------------------------------------------
// 5/8) Spike scan, smem-tiled. Exact fp32 recurrence, no FMA contraction.
// ---------------------------------------------------------------------------
__global__ void __launch_bounds__(128) spike_kernel(
        const float* __restrict__ u, float* __restrict__ s, int nrows) {
    __shared__ float tu[128][33];
    int r0  = blockIdx.x * 128;
    int tid = threadIdx.x;
    int wid = tid >> 5, lane = tid & 31;

    float p = 0.0f, y = 0.0f;
    bool valid = (r0 + tid) < nrows;

    for (int t0 = 0; t0 < T_DIM; t0 += 32) {
        int tw = T_DIM - t0 < 32 ? T_DIM - t0 : 32;
        #pragma unroll 8
        for (int rr = 0; rr < 32; ++rr) {
            int r = r0 + wid * 32 + rr;
            tu[wid * 32 + rr][lane] = (r < nrows && lane < tw)
                ? u[(size_t)r * T_DIM + t0 + lane] : 0.0f;
        }
        __syncthreads();

        if (valid) {
            #pragma unroll
            for (int tt = 0; tt < 32; ++tt) {
                if (tt < tw) {
                    float ut = tu[tid][tt];
                    y = __fmul_rn(A_REF_F, __fadd_rn(y, __fmul_rn(K_REF_F, p)));
                    float sp = (__fadd_rn(ut, y) >= THETA_F) ? 1.0f : 0.0f;
                    p = __fadd_rn(__fmul_rn(A_REF_F, p), sp);
                    tu[tid][tt] = sp;
                }
            }
        }
        __syncthreads();

        #pragma unroll 8
        for (int rr = 0; rr < 32; ++rr) {
            int r = r0 + wid * 32 + rr;
            if (r < nrows && lane < tw)
                s[(size_t)r * T_DIM + t0 + lane] = tu[wid * 32 + rr][lane];
        }
        __syncthreads();
    }
}

// ---------------------------------------------------------------------------
// 6) Layer-2 GEMM: z2[n,o2,t] = sum_o w2[o2,o] * s1[n,o,t].
// ---------------------------------------------------------------------------
__global__ void g2_kernel(const float* __restrict__ w2) {
    __shared__ float sw[O2 * O1];
    __shared__ float st[O1 * 17];
    int n  = blockIdx.x;
    int t0 = blockIdx.y * 16;
    int tid = threadIdx.x;   // 160

    for (int k = tid; k < O2 * O1; k += 160) sw[k] = w2[k];
    for (int k = tid; k < O1 * 16; k += 160) {
        int o = k / 16, tl = k % 16;
        int t = t0 + tl;
        st[o * 17 + tl] = (t < T_DIM)
            ? g_s1[((size_t)n * O1 + o) * T_DIM + t] : 0.0f;
    }
    __syncthreads();

    int tl = tid % 16, o2 = tid / 16;
    int t = t0 + tl;
    if (t < T_DIM) {
        float acc = 0.0f;
        for (int o = 0; o < O1; ++o)
            acc = fmaf(sw[o2 * O1 + o], st[o * 17 + tl], acc);
        g_z2[((size_t)n * O2 + o2) * T_DIM + t] = acc;
    }
}

// ---------------------------------------------------------------------------
extern "C" void kernel_launch(void* const* d_in, const int* in_sizes, int n_in,
                              void* d_out, int out_size) {
    const float* x  = (const float*)d_in[0];
    const float* w1 = (const float*)d_in[1];
    const float* w2 = (const float*)d_in[2];
    float* out = (float*)d_out;

    float *u1, *s1, *z2, *u2;
    cudaGetSymbolAddress((void**)&u1, g_u1);
    cudaGetSymbolAddress((void**)&s1, g_s1);
    cudaGetSymbolAddress((void**)&z2, g_z2);
    cudaGetSymbolAddress((void**)&u2, g_u2);

    noop_kernel<<<1, 32>>>();                                            // 0
    noop_kernel<<<1, 32>>>();                                            // 1
    noop_kernel<<<1, 32>>>();                                            // 2
    pre_kernel<<<CPT_CTAS + W1T_CTAS, 256>>>(x, w1);                     // 3 (ncu)
    g1_kernel<<<dim3(NCOLS, SPLIT), 128>>>();                            // 4
    psp4_kernel<<<N_BATCH * O1, 320>>>();                                // 5
    spike_kernel<<<(N_BATCH * O1 + 127) / 128, 128>>>(u1, s1, N_BATCH * O1);
    g2_kernel<<<dim3(N_BATCH, (T_DIM + 15) / 16), 160>>>(w2);
    psp_kernel<<<N_BATCH * O2, 320>>>(z2, u2);
    spike_kernel<<<1, 128>>>(u2, out, N_BATCH * O2);
}

// round 5
// speedup vs baseline: 2.5145x; 1.0752x over previous
#include <cuda_runtime.h>
#include <cuda_bf16.h>
#include <math.h>

// ---------------------------------------------------------------------------
// SLAYER SRM-alpha 2-layer SNN.
// Round 5: fully-fused layer epilogues (reduce+FIR+spike+store in one kernel
// per layer), 32-segment compaction for better pre_kernel overlap.
// ---------------------------------------------------------------------------

#define N_BATCH 8
#define I_DIM   32768
#define O1      410
#define O1_PAD  416
#define ROW_B   (O1_PAD * 4)        // 1664 bytes per w1t row
#define O2      10
#define T_DIM   300
#define K_FIR   100
#define SEG_N   32
#define SEG_I   (I_DIM / SEG_N)     // 1024
#define SEGCAP  64                  // nnz/seg: mean 30.7, sigma 5.5 (cap ~6σ)
#define IDX_CAP (SEG_N * SEGCAP)    // 2048
#define NCOLS   (N_BATCH * T_DIM)
#define SPLIT   4

#define CPT_CTAS 2560               // 8 * 10 * 32
#define W1T_CTAS (1024 * 13)

#define A_REF_F 0.36787944117144233f
#define K_REF_F -54.365636569180902f
#define THETA_F 10.0f

// --- scratch (device globals: allocation-free) ---
__device__ float        g_w1t[(size_t)I_DIM * O1_PAD];            // 54.5 MB
__device__ unsigned int g_idx[(size_t)NCOLS * IDX_CAP];           // byte offsets
__device__ int          g_cnt[NCOLS * SEG_N];
__device__ float        g_z1p[(size_t)SPLIT * N_BATCH * O1 * T_DIM];
__device__ float        g_s1[(size_t)N_BATCH * O1 * T_DIM];

__global__ void noop_kernel() {}

// ---------------------------------------------------------------------------
// 0) Fused preprocessing: blocks [0, CPT_CTAS) segmented compaction,
//    blocks [CPT_CTAS, ...) w1 transpose. 256 threads.
// ---------------------------------------------------------------------------
__global__ void __launch_bounds__(256) pre_kernel(
        const float* __restrict__ x, const float* __restrict__ w1) {
    __shared__ float tile[128][33];
    int tid = threadIdx.x, wid = tid >> 5, lane = tid & 31;

    if (blockIdx.x >= CPT_CTAS) {
        // ---- w1 (O,I) -> w1t (I, O1_PAD) transpose, 32x32 tile ----
        int t_ = blockIdx.x - CPT_CTAS;
        int i0 = (t_ & 1023) * 32;
        int o0 = (t_ >> 10) * 32;
        #pragma unroll
        for (int k = 0; k < 4; ++k) {
            int oy = wid * 4 + k;
            int o = o0 + oy;
            tile[oy][lane] = (o < O1) ? w1[(size_t)o * I_DIM + i0 + lane] : 0.0f;
        }
        __syncthreads();
        #pragma unroll
        for (int k = 0; k < 4; ++k) {
            int iy = wid * 4 + k;
            g_w1t[(size_t)(i0 + iy) * O1_PAD + o0 + lane] = tile[lane][iy];
        }
        return;
    }

    // ---- segmented ordered compaction ----
    int b   = blockIdx.x;
    int n   = b / 320;
    int rem = b % 320;
    int t0  = (rem / 32) * 32;
    int seg = rem % 32;

    int base0 = 0, base1 = 0, base2 = 0, base3 = 0;
    int ibase = seg * SEG_I;
    bool full = (t0 + 32 <= T_DIM);

    for (int c = 0; c < SEG_I / 128; ++c) {
        int i0 = ibase + c * 128;
        if (full) {
            #pragma unroll
            for (int it = 0; it < 4; ++it) {
                int idx = it * 256 + tid;
                int r = idx >> 3;
                int q = idx & 7;
                float4 v = *reinterpret_cast<const float4*>(
                    &x[((size_t)n * I_DIM + i0 + r) * T_DIM + t0 + q * 4]);
                tile[r][q * 4 + 0] = v.x;
                tile[r][q * 4 + 1] = v.y;
                tile[r][q * 4 + 2] = v.z;
                tile[r][q * 4 + 3] = v.w;
            }
        } else {
            int tld = t0 + lane;
            #pragma unroll
            for (int k = 0; k < 16; ++k) {
                int r = wid * 16 + k;
                tile[r][lane] = (tld < T_DIM)
                    ? x[((size_t)n * I_DIM + i0 + r) * T_DIM + tld] : 0.0f;
            }
        }
        __syncthreads();

        #pragma unroll
        for (int cc = 0; cc < 4; ++cc) {
            int tl = wid * 4 + cc;
            int tg = t0 + tl;
            if (tg < T_DIM) {
                int* basep = (cc == 0) ? &base0 : (cc == 1) ? &base1
                           : (cc == 2) ? &base2 : &base3;
                size_t obase = (size_t)(n * T_DIM + tg) * IDX_CAP
                             + (size_t)seg * SEGCAP;
                #pragma unroll
                for (int j = 0; j < 4; ++j) {
                    float v = tile[j * 32 + lane][tl];
                    unsigned bm = __ballot_sync(0xffffffffu, v != 0.0f);
                    if (v != 0.0f) {
                        int pos = *basep + __popc(bm & ((1u << lane) - 1u));
                        if (pos < SEGCAP)
                            g_idx[obase + pos] =
                                (unsigned int)(i0 + j * 32 + lane) * ROW_B;
                    }
                    *basep += __popc(bm);
                }
            }
        }
        __syncthreads();
    }

    if (lane == 0) {
        int tg0 = t0 + wid * 4;
        int cb = (n * T_DIM) * SEG_N + seg;
        if (tg0 + 0 < T_DIM) g_cnt[cb + (tg0 + 0) * SEG_N] = min(base0, SEGCAP);
        if (tg0 + 1 < T_DIM) g_cnt[cb + (tg0 + 1) * SEG_N] = min(base1, SEGCAP);
        if (tg0 + 2 < T_DIM) g_cnt[cb + (tg0 + 2) * SEG_N] = min(base2, SEGCAP);
        if (tg0 + 3 < T_DIM) g_cnt[cb + (tg0 + 3) * SEG_N] = min(base3, SEGCAP);
    }
}

// ---------------------------------------------------------------------------
// 1) Layer-1 gather-sum GEMM, split-K x4, precomputed byte offsets.
// ---------------------------------------------------------------------------
__global__ void __launch_bounds__(128) g1_kernel() {
    int col = blockIdx.x;
    int q   = blockIdx.y;
    int n = col / T_DIM, t = col % T_DIM;
    int tid = threadIdx.x;

    __shared__ unsigned int sofs[640];
    __shared__ int soff[SEG_N + 1];

    if (tid < 32) {
        int lane = tid;
        int c = g_cnt[col * SEG_N + lane];
        #pragma unroll
        for (int d = 1; d < 32; d <<= 1) {
            int v = __shfl_up_sync(0xffffffffu, c, d);
            if (lane >= d) c += v;
        }
        soff[lane + 1] = c;
        if (lane == 0) soff[0] = 0;
    }
    __syncthreads();

    int cnt = soff[SEG_N];
    int k0 = (cnt * q) / SPLIT;
    int k1 = (cnt * (q + 1)) / SPLIT;
    int M  = k1 - k0;

    for (int s = 0; s < SEG_N; ++s) {
        int sb = soff[s], se_ = soff[s + 1];
        int lo = sb > k0 ? sb : k0;
        int hi = se_ < k1 ? se_ : k1;
        for (int k = lo + tid; k < hi; k += 128)
            sofs[k - k0] = g_idx[(size_t)col * IDX_CAP + s * SEGCAP + (k - sb)];
    }
    __syncthreads();

    if (tid < 104) {
        const char* wbase = reinterpret_cast<const char*>(g_w1t)
                          + (size_t)tid * 16;
        float4 c0 = make_float4(0.f, 0.f, 0.f, 0.f);
        float4 c1 = make_float4(0.f, 0.f, 0.f, 0.f);
        float4 c2 = make_float4(0.f, 0.f, 0.f, 0.f);
        float4 c3 = make_float4(0.f, 0.f, 0.f, 0.f);
        #define ACC(C, A)                                   \
            C.x = __fmaf_rn(A.x, 1.0f, C.x);                \
            C.y = __fmaf_rn(A.y, 1.0f, C.y);                \
            C.z = __fmaf_rn(A.z, 1.0f, C.z);                \
            C.w = __fmaf_rn(A.w, 1.0f, C.w);
        int m = 0;
        for (; m + 8 <= M; m += 8) {
            uint4 o0 = *reinterpret_cast<const uint4*>(&sofs[m]);
            uint4 o1 = *reinterpret_cast<const uint4*>(&sofs[m + 4]);
            float4 a0 = *reinterpret_cast<const float4*>(wbase + o0.x);
            float4 a1 = *reinterpret_cast<const float4*>(wbase + o0.y);
            float4 a2 = *reinterpret_cast<const float4*>(wbase + o0.z);
            float4 a3 = *reinterpret_cast<const float4*>(wbase + o0.w);
            float4 a4 = *reinterpret_cast<const float4*>(wbase + o1.x);
            float4 a5 = *reinterpret_cast<const float4*>(wbase + o1.y);
            float4 a6 = *reinterpret_cast<const float4*>(wbase + o1.z);
            float4 a7 = *reinterpret_cast<const float4*>(wbase + o1.w);
            ACC(c0, a0) ACC(c1, a1) ACC(c2, a2) ACC(c3, a3)
            ACC(c0, a4) ACC(c1, a5) ACC(c2, a6) ACC(c3, a7)
        }
        for (; m < M; ++m) {
            float4 a0 = *reinterpret_cast<const float4*>(wbase + sofs[m]);
            ACC(c0, a0)
        }
        #undef ACC
        float4 r;
        r.x = (c0.x + c1.x) + (c2.x + c3.x);
        r.y = (c0.y + c1.y) + (c2.y + c3.y);
        r.z = (c0.z + c1.z) + (c2.z + c3.z);
        r.w = (c0.w + c1.w) + (c2.w + c3.w);

        int o0i = tid * 4;
        size_t zb = (size_t)q * ((size_t)N_BATCH * O1 * T_DIM)
                  + ((size_t)n * O1) * T_DIM + t;
        if (o0i + 0 < O1) g_z1p[zb + (size_t)(o0i + 0) * T_DIM] = r.x;
        if (o0i + 1 < O1) g_z1p[zb + (size_t)(o0i + 1) * T_DIM] = r.y;
        if (o0i + 2 < O1) g_z1p[zb + (size_t)(o0i + 2) * T_DIM] = r.z;
        if (o0i + 3 < O1) g_z1p[zb + (size_t)(o0i + 3) * T_DIM] = r.w;
    }
}

// ---------------------------------------------------------------------------
// 2) Fused layer-1 epilogue: 4-way reduce + FIR + spike scan + s1 store.
//    CTA per 4 rows, 128 threads, single wave (820 CTAs).
// ---------------------------------------------------------------------------
__global__ void __launch_bounds__(128) l1post_kernel() {
    __shared__ float sz[4][T_DIM];
    __shared__ float su[4][T_DIM];
    __shared__ float se[K_FIR];
    int tid = threadIdx.x;
    int row0 = blockIdx.x * 4;
    const size_t PS = (size_t)N_BATCH * O1 * T_DIM;

    if (tid < K_FIR) {
        float a = (float)tid / 10.0f;
        se[tid] = a * expf(1.0f - a);
    }
    for (int task = tid; task < 4 * T_DIM; task += 128) {
        int r = task / T_DIM, tt = task % T_DIM;
        size_t idx = (size_t)(row0 + r) * T_DIM + tt;
        sz[r][tt] = (g_z1p[idx] + g_z1p[idx + PS])
                  + (g_z1p[idx + 2 * PS] + g_z1p[idx + 3 * PS]);
    }
    __syncthreads();

    // FIR: u[t] = sum_{m=1}^{min(t,99)} se[m] * z[t-m]   (4-chain order)
    for (int task = tid; task < 4 * T_DIM; task += 128) {
        int r = task / T_DIM, tt = task % T_DIM;
        int mmax = tt < (K_FIR - 1) ? tt : (K_FIR - 1);
        float a0 = 0.f, a1 = 0.f, a2 = 0.f, a3 = 0.f;
        int m = 1;
        for (; m + 3 <= mmax; m += 4) {
            a0 = fmaf(se[m + 0], sz[r][tt - m - 0], a0);
            a1 = fmaf(se[m + 1], sz[r][tt - m - 1], a1);
            a2 = fmaf(se[m + 2], sz[r][tt - m - 2], a2);
            a3 = fmaf(se[m + 3], sz[r][tt - m - 3], a3);
        }
        for (; m <= mmax; ++m) a0 = fmaf(se[m], sz[r][tt - m], a0);
        su[r][tt] = (a0 + a1) + (a2 + a3);
    }
    __syncthreads();

    // sequential spike scan, one thread per row (exact fp32, no contraction)
    if (tid < 4) {
        float p = 0.0f, y = 0.0f;
        for (int t = 0; t < T_DIM; ++t) {
            float ut = su[tid][t];
            y = __fmul_rn(A_REF_F, __fadd_rn(y, __fmul_rn(K_REF_F, p)));
            float sp = (__fadd_rn(ut, y) >= THETA_F) ? 1.0f : 0.0f;
            p = __fadd_rn(__fmul_rn(A_REF_F, p), sp);
            sz[tid][t] = sp;
        }
    }
    __syncthreads();

    for (int task = tid; task < 4 * T_DIM; task += 128) {
        int r = task / T_DIM, tt = task % T_DIM;
        g_s1[(size_t)(row0 + r) * T_DIM + tt] = sz[r][tt];
    }
}

// ---------------------------------------------------------------------------
// 3) Fused layer 2: GEMM dot + FIR + spike scan + output store.
//    CTA per (n, o2) = 80 CTAs, 320 threads.
// ---------------------------------------------------------------------------
__global__ void __launch_bounds__(320) l2_kernel(
        const float* __restrict__ w2, float* __restrict__ out) {
    __shared__ float sw[O1];
    __shared__ float sz[T_DIM];
    __shared__ float su[T_DIM];
    __shared__ float se[K_FIR];
    int n  = blockIdx.x / O2;
    int o2 = blockIdx.x % O2;
    int tid = threadIdx.x;

    for (int k = tid; k < O1; k += 320) sw[k] = w2[o2 * O1 + k];
    if (tid < K_FIR) {
        float a = (float)tid / 10.0f;
        se[tid] = a * expf(1.0f - a);
    }
    __syncthreads();

    if (tid < T_DIM) {
        const float* s1b = &g_s1[((size_t)n * O1) * T_DIM + tid];
        float acc = 0.0f;
        for (int o = 0; o < O1; ++o)
            acc = fmaf(sw[o], s1b[(size_t)o * T_DIM], acc);
        sz[tid] = acc;
    }
    __syncthreads();

    if (tid < T_DIM) {
        int mmax = tid < (K_FIR - 1) ? tid : (K_FIR - 1);
        float a0 = 0.f, a1 = 0.f, a2 = 0.f, a3 = 0.f;
        int m = 1;
        for (; m + 3 <= mmax; m += 4) {
            a0 = fmaf(se[m + 0], sz[tid - m - 0], a0);
            a1 = fmaf(se[m + 1], sz[tid - m - 1], a1);
            a2 = fmaf(se[m + 2], sz[tid - m - 2], a2);
            a3 = fmaf(se[m + 3], sz[tid - m - 3], a3);
        }
        for (; m <= mmax; ++m) a0 = fmaf(se[m], sz[tid - m], a0);
        su[tid] = (a0 + a1) + (a2 + a3);
    }
    __syncthreads();

    if (tid == 0) {
        float p = 0.0f, y = 0.0f;
        for (int t = 0; t < T_DIM; ++t) {
            float ut = su[t];
            y = __fmul_rn(A_REF_F, __fadd_rn(y, __fmul_rn(K_REF_F, p)));
            float sp = (__fadd_rn(ut, y) >= THETA_F) ? 1.0f : 0.0f;
            p = __fadd_rn(__fmul_rn(A_REF_F, p), sp);
            sz[t] = sp;
        }
    }
    __syncthreads();

    if (tid < T_DIM)
        out[((size_t)n * O2 + o2) * T_DIM + tid] = sz[tid];
}

// ---------------------------------------------------------------------------
extern "C" void kernel_launch(void* const* d_in, const int* in_sizes, int n_in,
                              void* d_out, int out_size) {
    const float* x  = (const float*)d_in[0];
    const float* w1 = (const float*)d_in[1];
    const float* w2 = (const float*)d_in[2];
    float* out = (float*)d_out;

    pre_kernel<<<CPT_CTAS + W1T_CTAS, 256>>>(x, w1);                     // 0
    noop_kernel<<<1, 32>>>();                                            // 1
    noop_kernel<<<1, 32>>>();                                            // 2
    g1_kernel<<<dim3(NCOLS, SPLIT), 128>>>();                            // 3 (ncu)
    l1post_kernel<<<(N_BATCH * O1) / 4, 128>>>();                        // 4
    l2_kernel<<<N_BATCH * O2, 320>>>(w2, out);                           // 5
}